// round 2
// baseline (speedup 1.0000x reference)
#include <cuda_runtime.h>

#define S_DIM 128
#define N_DIM 256
#define CM 256
#define CH 32
#define CZ 128
#define P_DIM (N_DIM * CH)   // 8192

#define LN_EPS 1e-5f
#define OPM_EPS 1e-3f

// ---- scratch (static __device__, allocation-free) ----
__device__ float g_a[P_DIM * S_DIM];               // a_t[p][s], p = n*32+h   (4 MB)
__device__ float g_b[P_DIM * S_DIM];               // b_t[q][s]               (4 MB)
__device__ float g_O[(size_t)P_DIM * P_DIM];       // outer accumulator       (256 MB)
__device__ float g_norm[N_DIM * N_DIM];            // mask^T mask + eps

// ============================================================================
// Kernel 1: LayerNorm + dual projection + mask.  One block per (s, n) row.
// ============================================================================
__global__ void ln_proj_kernel(const float* __restrict__ m,
                               const float* __restrict__ mask,
                               const float* __restrict__ ln_w,
                               const float* __restrict__ ln_b,
                               const float* __restrict__ w1,
                               const float* __restrict__ b1,
                               const float* __restrict__ w2,
                               const float* __restrict__ b2) {
    const int row = blockIdx.x;            // s*N + n
    const int s = row >> 8;                // row / 256
    const int n = row & 255;
    const int tid = threadIdx.x;           // 256 threads, one per c_m element

    __shared__ float sh_ln[CM];
    __shared__ float wsum[8], wsum2[8];
    __shared__ float s_mu, s_rstd;
    __shared__ float part[4][64];

    float x = m[(size_t)row * CM + tid];

    // block reduction for mean / var
    float v = x, v2 = x * x;
    #pragma unroll
    for (int o = 16; o > 0; o >>= 1) {
        v  += __shfl_xor_sync(0xffffffff, v,  o);
        v2 += __shfl_xor_sync(0xffffffff, v2, o);
    }
    const int warp = tid >> 5, lane = tid & 31;
    if (lane == 0) { wsum[warp] = v; wsum2[warp] = v2; }
    __syncthreads();
    if (tid == 0) {
        float t = 0.f, t2 = 0.f;
        #pragma unroll
        for (int i = 0; i < 8; i++) { t += wsum[i]; t2 += wsum2[i]; }
        float mu  = t * (1.0f / CM);
        float var = t2 * (1.0f / CM) - mu * mu;
        s_mu = mu;
        s_rstd = rsqrtf(var + LN_EPS);
    }
    __syncthreads();

    sh_ln[tid] = (x - s_mu) * s_rstd * ln_w[tid] + ln_b[tid];
    __syncthreads();

    // 64 outputs (32 for a, 32 for b); 4 partial-sum groups over c_m quarters
    const int g = tid >> 6;        // 0..3  (k-quarter)
    const int o = tid & 63;        // output id
    const int h = o & 31;
    const float* __restrict__ w = (o < 32) ? w1 : w2;
    float acc = 0.f;
    const int k0 = g * 64;
    #pragma unroll 16
    for (int k = k0; k < k0 + 64; k++)
        acc += sh_ln[k] * w[k * CH + h];
    part[g][o] = acc;
    __syncthreads();

    if (tid < 64) {
        float mk = mask[s * N_DIM + n];
        float sum = part[0][tid] + part[1][tid] + part[2][tid] + part[3][tid];
        if (tid < 32) {
            g_a[(size_t)(n * CH + tid) * S_DIM + s] = (sum + b1[tid]) * mk;
        } else {
            g_b[(size_t)(n * CH + h) * S_DIM + s] = (sum + b2[h]) * mk;
        }
    }
}

// ============================================================================
// Kernel 2: norm[i][j] = sum_s mask[s][i]*mask[s][j] + eps
// ============================================================================
__global__ void norm_kernel(const float* __restrict__ mask) {
    const int i = blockIdx.x;
    const int j = threadIdx.x;     // 256
    __shared__ float mi[S_DIM];
    if (j < S_DIM) mi[j] = mask[j * N_DIM + i];
    __syncthreads();
    float acc = 0.f;
    #pragma unroll 8
    for (int s = 0; s < S_DIM; s++)
        acc += mi[s] * mask[s * N_DIM + j];
    g_norm[i * N_DIM + j] = acc + OPM_EPS;
}

// ============================================================================
// Kernel 3: O[8192,8192] = A[8192,128] * B[8192,128]^T   (both K-contiguous)
// 128x128 block tile, 8x8 microtile, BK=16, double-buffered smem.
// ============================================================================
__global__ void __launch_bounds__(256, 2) gemm1_kernel() {
    const int p0 = blockIdx.y * 128;
    const int q0 = blockIdx.x * 128;

    __shared__ float As[2][16][132];
    __shared__ float Bs[2][16][132];

    const int tid = threadIdx.x;
    const int tx = tid & 15, ty = tid >> 4;
    const int lp = tid >> 2;              // 0..63 (row within tile; +64 second pass)
    const int lk = (tid & 3) * 4;         // 0,4,8,12 (k offset within chunk)

    float acc[8][8];
    #pragma unroll
    for (int i = 0; i < 8; i++)
        #pragma unroll
        for (int j = 0; j < 8; j++) acc[i][j] = 0.f;

    float4 ra[2], rb[2];

    // prologue: chunk 0
    #pragma unroll
    for (int it = 0; it < 2; it++) {
        int p = lp + it * 64;
        ra[it] = *(const float4*)&g_a[(size_t)(p0 + p) * S_DIM + lk];
        rb[it] = *(const float4*)&g_b[(size_t)(q0 + p) * S_DIM + lk];
    }
    #pragma unroll
    for (int it = 0; it < 2; it++) {
        int p = lp + it * 64;
        As[0][lk + 0][p] = ra[it].x; As[0][lk + 1][p] = ra[it].y;
        As[0][lk + 2][p] = ra[it].z; As[0][lk + 3][p] = ra[it].w;
        Bs[0][lk + 0][p] = rb[it].x; Bs[0][lk + 1][p] = rb[it].y;
        Bs[0][lk + 2][p] = rb[it].z; Bs[0][lk + 3][p] = rb[it].w;
    }
    __syncthreads();

    int buf = 0;
    for (int kc = 0; kc < S_DIM; kc += 16) {
        const int next = kc + 16;
        if (next < S_DIM) {
            #pragma unroll
            for (int it = 0; it < 2; it++) {
                int p = lp + it * 64;
                ra[it] = *(const float4*)&g_a[(size_t)(p0 + p) * S_DIM + next + lk];
                rb[it] = *(const float4*)&g_b[(size_t)(q0 + p) * S_DIM + next + lk];
            }
        }
        #pragma unroll
        for (int kk = 0; kk < 16; kk++) {
            float4 a0 = *(const float4*)&As[buf][kk][ty * 4];
            float4 a1 = *(const float4*)&As[buf][kk][ty * 4 + 64];
            float4 b0 = *(const float4*)&Bs[buf][kk][tx * 4];
            float4 b1 = *(const float4*)&Bs[buf][kk][tx * 4 + 64];
            float ar[8] = {a0.x, a0.y, a0.z, a0.w, a1.x, a1.y, a1.z, a1.w};
            float br[8] = {b0.x, b0.y, b0.z, b0.w, b1.x, b1.y, b1.z, b1.w};
            #pragma unroll
            for (int i = 0; i < 8; i++)
                #pragma unroll
                for (int j = 0; j < 8; j++)
                    acc[i][j] += ar[i] * br[j];
        }
        if (next < S_DIM) {
            const int nb = buf ^ 1;
            #pragma unroll
            for (int it = 0; it < 2; it++) {
                int p = lp + it * 64;
                As[nb][lk + 0][p] = ra[it].x; As[nb][lk + 1][p] = ra[it].y;
                As[nb][lk + 2][p] = ra[it].z; As[nb][lk + 3][p] = ra[it].w;
                Bs[nb][lk + 0][p] = rb[it].x; Bs[nb][lk + 1][p] = rb[it].y;
                Bs[nb][lk + 2][p] = rb[it].z; Bs[nb][lk + 3][p] = rb[it].w;
            }
            __syncthreads();
            buf = nb;
        }
    }

    #pragma unroll
    for (int rg = 0; rg < 2; rg++)
        #pragma unroll
        for (int e = 0; e < 4; e++) {
            const int r = rg * 64 + ty * 4 + e;
            const int ri = rg * 4 + e;
            const size_t base = (size_t)(p0 + r) * P_DIM + q0;
            float4 o0 = make_float4(acc[ri][0], acc[ri][1], acc[ri][2], acc[ri][3]);
            float4 o1 = make_float4(acc[ri][4], acc[ri][5], acc[ri][6], acc[ri][7]);
            *(float4*)&g_O[base + tx * 4]      = o0;
            *(float4*)&g_O[base + tx * 4 + 64] = o1;
        }
}

// ============================================================================
// Kernel 4: out[65536,128] = O'[65536,1024] @ wo[1024,128]  (+bo, /norm)
// O'[m][k] = g_O[(i*32 + k/32)*8192 + (m%256)*32 + k%32],  m = i*256 + j
// ============================================================================
__global__ void __launch_bounds__(256, 2) gemm2_kernel(const float* __restrict__ wo,
                                                       const float* __restrict__ bo,
                                                       float* __restrict__ out) {
    const int m0 = blockIdx.x * 128;
    const int i_idx = m0 >> 8;          // fixed i for this block (128 | 256)
    const int j0 = m0 & 255;            // 0 or 128

    __shared__ float As[2][16][132];
    __shared__ float Bs[2][16][132];

    const int tid = threadIdx.x;
    const int tx = tid & 15, ty = tid >> 4;
    const int lr = tid >> 2;              // 0..63
    const int lk = (tid & 3) * 4;         // 0,4,8,12
    const int lbk = tid >> 5;             // 0..7  (+8 second pass)
    const int lbz = (tid & 31) * 4;       // 0..124

    float acc[8][8];
    #pragma unroll
    for (int i = 0; i < 8; i++)
        #pragma unroll
        for (int j = 0; j < 8; j++) acc[i][j] = 0.f;

    float4 ra[2], rb[2];

    // prologue: chunk kc = 0  (c = 0, d0 = 0)
    {
        const size_t rowbase = (size_t)(i_idx * 32) * P_DIM;
        #pragma unroll
        for (int it = 0; it < 2; it++) {
            int r = lr + it * 64;
            ra[it] = *(const float4*)&g_O[rowbase + (size_t)(j0 + r) * 32 + lk];
            rb[it] = *(const float4*)&wo[(lbk + it * 8) * CZ + lbz];
        }
        #pragma unroll
        for (int it = 0; it < 2; it++) {
            int r = lr + it * 64;
            As[0][lk + 0][r] = ra[it].x; As[0][lk + 1][r] = ra[it].y;
            As[0][lk + 2][r] = ra[it].z; As[0][lk + 3][r] = ra[it].w;
            *(float4*)&Bs[0][lbk + it * 8][lbz] = rb[it];
        }
    }
    __syncthreads();

    int buf = 0;
    #pragma unroll 1
    for (int kc = 0; kc < CH * CH; kc += 16) {
        const int next = kc + 16;
        if (next < CH * CH) {
            const size_t rowbase = (size_t)(i_idx * 32 + (next >> 5)) * P_DIM;
            const int d0 = next & 31;
            #pragma unroll
            for (int it = 0; it < 2; it++) {
                int r = lr + it * 64;
                ra[it] = *(const float4*)&g_O[rowbase + (size_t)(j0 + r) * 32 + d0 + lk];
                rb[it] = *(const float4*)&wo[(next + lbk + it * 8) * CZ + lbz];
            }
        }
        #pragma unroll
        for (int kk = 0; kk < 16; kk++) {
            float4 a0 = *(const float4*)&As[buf][kk][ty * 4];
            float4 a1 = *(const float4*)&As[buf][kk][ty * 4 + 64];
            float4 b0 = *(const float4*)&Bs[buf][kk][tx * 4];
            float4 b1 = *(const float4*)&Bs[buf][kk][tx * 4 + 64];
            float ar[8] = {a0.x, a0.y, a0.z, a0.w, a1.x, a1.y, a1.z, a1.w};
            float br[8] = {b0.x, b0.y, b0.z, b0.w, b1.x, b1.y, b1.z, b1.w};
            #pragma unroll
            for (int i = 0; i < 8; i++)
                #pragma unroll
                for (int j = 0; j < 8; j++)
                    acc[i][j] += ar[i] * br[j];
        }
        if (next < CH * CH) {
            const int nb = buf ^ 1;
            #pragma unroll
            for (int it = 0; it < 2; it++) {
                int r = lr + it * 64;
                As[nb][lk + 0][r] = ra[it].x; As[nb][lk + 1][r] = ra[it].y;
                As[nb][lk + 2][r] = ra[it].z; As[nb][lk + 3][r] = ra[it].w;
                *(float4*)&Bs[nb][lbk + it * 8][lbz] = rb[it];
            }
            __syncthreads();
            buf = nb;
        }
    }

    // epilogue: + bo, / norm
    const int c0 = tx * 4;
    float bo0[4], bo1[4];
    #pragma unroll
    for (int e = 0; e < 4; e++) { bo0[e] = bo[c0 + e]; bo1[e] = bo[c0 + 64 + e]; }

    #pragma unroll
    for (int rg = 0; rg < 2; rg++)
        #pragma unroll
        for (int e = 0; e < 4; e++) {
            const int r = rg * 64 + ty * 4 + e;
            const int ri = rg * 4 + e;
            const int mrow = m0 + r;
            const float inv = 1.0f / g_norm[mrow];
            const size_t base = (size_t)mrow * CZ;
            float4 o0, o1;
            o0.x = (acc[ri][0] + bo0[0]) * inv;
            o0.y = (acc[ri][1] + bo0[1]) * inv;
            o0.z = (acc[ri][2] + bo0[2]) * inv;
            o0.w = (acc[ri][3] + bo0[3]) * inv;
            o1.x = (acc[ri][4] + bo1[0]) * inv;
            o1.y = (acc[ri][5] + bo1[1]) * inv;
            o1.z = (acc[ri][6] + bo1[2]) * inv;
            o1.w = (acc[ri][7] + bo1[3]) * inv;
            *(float4*)&out[base + c0]      = o0;
            *(float4*)&out[base + c0 + 64] = o1;
        }
}

// ============================================================================
extern "C" void kernel_launch(void* const* d_in, const int* in_sizes, int n_in,
                              void* d_out, int out_size) {
    const float* m    = (const float*)d_in[0];
    const float* mask = (const float*)d_in[1];
    const float* ln_w = (const float*)d_in[2];
    const float* ln_b = (const float*)d_in[3];
    const float* w1   = (const float*)d_in[4];
    const float* b1   = (const float*)d_in[5];
    const float* w2   = (const float*)d_in[6];
    const float* b2   = (const float*)d_in[7];
    const float* wo   = (const float*)d_in[8];
    const float* bo   = (const float*)d_in[9];
    float* out = (float*)d_out;

    ln_proj_kernel<<<S_DIM * N_DIM, 256>>>(m, mask, ln_w, ln_b, w1, b1, w2, b2);
    norm_kernel<<<N_DIM, 256>>>(mask);

    dim3 g1(P_DIM / 128, P_DIM / 128);   // 64 x 64
    gemm1_kernel<<<g1, 256>>>();

    gemm2_kernel<<<(N_DIM * N_DIM) / 128, 256>>>(wo, bo, out);
}

// round 4
// speedup vs baseline: 1.7801x; 1.7801x over previous
#include <cuda_runtime.h>
#include <cstdint>

#define S_DIM 128
#define N_DIM 256
#define CM 256
#define CH 32
#define CZ 128
#define P_DIM 8192
#define LN_EPS 1e-5f
#define OPM_EPS 1e-3f

__device__ __align__(16) float g_a[P_DIM * S_DIM];          // [p=(n,h)][s] tf32-rounded
__device__ __align__(16) float g_b[P_DIM * S_DIM];          // [q=(n,h)][s] tf32-rounded
__device__ __align__(16) float g_O[(size_t)P_DIM * P_DIM];  // [(i,c)][(j,d)] tf32-rounded
__device__ __align__(16) float g_woT[CZ * CH * CH];         // [z][k=(c,d)] tf32-rounded
__device__ float g_norm[N_DIM * N_DIM];

__device__ __forceinline__ uint32_t rna_tf32(float x) {
    uint32_t r;
    asm("cvt.rna.tf32.f32 %0, %1;" : "=r"(r) : "f"(x));
    return r;
}

// D += A(16x8, tf32 row) * B(8x8, tf32 col)
__device__ __forceinline__ void mma_tf32(float* c, const uint32_t* a, const uint32_t* b) {
    asm volatile(
        "mma.sync.aligned.m16n8k8.row.col.f32.tf32.tf32.f32 "
        "{%0,%1,%2,%3}, {%4,%5,%6,%7}, {%8,%9}, {%0,%1,%2,%3};\n"
        : "+f"(c[0]), "+f"(c[1]), "+f"(c[2]), "+f"(c[3])
        : "r"(a[0]), "r"(a[1]), "r"(a[2]), "r"(a[3]), "r"(b[0]), "r"(b[1]));
}

// smem tile accessors: A[2][128][36], B[2][128][36] in dynamic smem (73728 B)
__device__ __forceinline__ float& As_(float* s, int buf, int m, int k) {
    return s[buf * 4608 + m * 36 + k];
}
__device__ __forceinline__ float& Bs_(float* s, int buf, int n, int k) {
    return s[9216 + buf * 4608 + n * 36 + k];
}

// ============================================================================
// Kernel 1: LayerNorm + dual 256->32 projection (weights cached in smem).
// 2048 blocks, each handles one s and a group of 16 n rows.
// ============================================================================
__global__ void __launch_bounds__(256) ln_proj_kernel(
        const float* __restrict__ m, const float* __restrict__ mask,
        const float* __restrict__ ln_w, const float* __restrict__ ln_b,
        const float* __restrict__ w1, const float* __restrict__ b1,
        const float* __restrict__ w2, const float* __restrict__ b2) {
    extern __shared__ __align__(16) float dsm[];
    float* sw1 = dsm;              // [256][32]
    float* sw2 = dsm + 8192;       // [256][32]
    float* sh_ln = dsm + 16384;    // [256]
    float* part = dsm + 16640;     // [4][64]
    __shared__ float wsum[8], wsum2[8], s_stats[2];

    const int s = blockIdx.x >> 4;
    const int grp = blockIdx.x & 15;
    const int tid = threadIdx.x;

    #pragma unroll
    for (int i = 0; i < 8; i++) {
        int f = tid + i * 256;
        *(float4*)&sw1[f * 4] = *(const float4*)&w1[f * 4];
        *(float4*)&sw2[f * 4] = *(const float4*)&w2[f * 4];
    }
    __syncthreads();

    const int g = tid >> 6, o = tid & 63, h = o & 31;
    const float* wsm = (o < 32) ? sw1 : sw2;
    const int k0 = g * 64;

    for (int r = 0; r < 16; r++) {
        const int n = grp * 16 + r;
        const int row = s * N_DIM + n;
        float x = m[(size_t)row * CM + tid];
        float v = x, v2 = x * x;
        #pragma unroll
        for (int off = 16; off > 0; off >>= 1) {
            v  += __shfl_xor_sync(0xffffffff, v,  off);
            v2 += __shfl_xor_sync(0xffffffff, v2, off);
        }
        if ((tid & 31) == 0) { wsum[tid >> 5] = v; wsum2[tid >> 5] = v2; }
        __syncthreads();
        if (tid == 0) {
            float t = 0.f, t2 = 0.f;
            #pragma unroll
            for (int i = 0; i < 8; i++) { t += wsum[i]; t2 += wsum2[i]; }
            float mu = t * (1.f / CM);
            float var = t2 * (1.f / CM) - mu * mu;
            s_stats[0] = mu; s_stats[1] = rsqrtf(var + LN_EPS);
        }
        __syncthreads();
        sh_ln[tid] = (x - s_stats[0]) * s_stats[1] * ln_w[tid] + ln_b[tid];
        __syncthreads();

        float acc = 0.f;
        #pragma unroll 16
        for (int k = k0; k < k0 + 64; k++)
            acc += sh_ln[k] * wsm[k * CH + h];
        part[g * 64 + o] = acc;
        __syncthreads();

        if (tid < 64) {
            float mk = mask[row];
            float sum = part[tid] + part[64 + tid] + part[128 + tid] + part[192 + tid];
            if (tid < 32)
                g_a[(size_t)(n * CH + tid) * S_DIM + s] =
                    __uint_as_float(rna_tf32((sum + b1[tid]) * mk));
            else
                g_b[(size_t)(n * CH + h) * S_DIM + s] =
                    __uint_as_float(rna_tf32((sum + b2[h]) * mk));
        }
        __syncthreads();
    }
}

// ============================================================================
// norm[i][j] = sum_s mask[s,i] mask[s,j] + eps ;  woT[z][k] = rna(wo[k][z])
// ============================================================================
__global__ void norm_kernel(const float* __restrict__ mask) {
    const int i = blockIdx.x, j = threadIdx.x;
    __shared__ float mi[S_DIM];
    if (j < S_DIM) mi[j] = mask[j * N_DIM + i];
    __syncthreads();
    float acc = 0.f;
    #pragma unroll 8
    for (int s = 0; s < S_DIM; s++) acc += mi[s] * mask[s * N_DIM + j];
    g_norm[i * N_DIM + j] = acc + OPM_EPS;
}

__global__ void woT_kernel(const float* __restrict__ wo) {
    int idx = blockIdx.x * 256 + threadIdx.x;   // 131072
    int z = idx >> 10, k = idx & 1023;
    g_woT[idx] = __uint_as_float(rna_tf32(wo[k * CZ + z]));
}

// ============================================================================
// GEMM1: O[8192,8192] = A[8192,128] * B[8192,128]^T  via mma.sync tf32
// CTA 128x128, 8 warps (2x4), warp tile 64x32, BK=32, double-buffered.
// ============================================================================
__global__ void __launch_bounds__(256) gemm1_mma() {
    extern __shared__ __align__(16) float sm[];
    const int tid = threadIdx.x;
    const int wid = tid >> 5, lane = tid & 31;
    const int wm = (wid & 1) * 64, wn = (wid >> 1) * 32;
    const int p0 = blockIdx.y * 128, q0 = blockIdx.x * 128;
    const int lr = tid >> 3;            // 0..31 (+32*i)
    const int lc = (tid & 7) * 4;       // 0..28

    float acc[4][4][4];
    #pragma unroll
    for (int a = 0; a < 4; a++)
        #pragma unroll
        for (int b = 0; b < 4; b++)
            #pragma unroll
            for (int e = 0; e < 4; e++) acc[a][b][e] = 0.f;

    float4 pa[4], pb[4];
    #pragma unroll
    for (int i = 0; i < 4; i++) {
        int r = lr + i * 32;
        pa[i] = *(const float4*)&g_a[(size_t)(p0 + r) * S_DIM + lc];
        pb[i] = *(const float4*)&g_b[(size_t)(q0 + r) * S_DIM + lc];
    }
    #pragma unroll
    for (int i = 0; i < 4; i++) {
        int r = lr + i * 32;
        *(float4*)&As_(sm, 0, r, lc) = pa[i];
        *(float4*)&Bs_(sm, 0, r, lc) = pb[i];
    }
    __syncthreads();

    int buf = 0;
    #pragma unroll
    for (int ch = 0; ch < 4; ch++) {
        if (ch < 3) {
            const int kb = (ch + 1) * 32;
            #pragma unroll
            for (int i = 0; i < 4; i++) {
                int r = lr + i * 32;
                pa[i] = *(const float4*)&g_a[(size_t)(p0 + r) * S_DIM + kb + lc];
                pb[i] = *(const float4*)&g_b[(size_t)(q0 + r) * S_DIM + kb + lc];
            }
        }
        #pragma unroll
        for (int kk = 0; kk < 4; kk++) {
            const int acol = kk * 8 + (lane & 3);
            const int arow = wm + (lane >> 2);
            uint32_t af[4][4], bf[4][2];
            #pragma unroll
            for (int mt = 0; mt < 4; mt++) {
                af[mt][0] = __float_as_uint(As_(sm, buf, arow + mt * 16,     acol));
                af[mt][1] = __float_as_uint(As_(sm, buf, arow + mt * 16 + 8, acol));
                af[mt][2] = __float_as_uint(As_(sm, buf, arow + mt * 16,     acol + 4));
                af[mt][3] = __float_as_uint(As_(sm, buf, arow + mt * 16 + 8, acol + 4));
            }
            const int brow = wn + (lane >> 2);
            #pragma unroll
            for (int nt = 0; nt < 4; nt++) {
                bf[nt][0] = __float_as_uint(Bs_(sm, buf, brow + nt * 8, acol));
                bf[nt][1] = __float_as_uint(Bs_(sm, buf, brow + nt * 8, acol + 4));
            }
            #pragma unroll
            for (int mt = 0; mt < 4; mt++)
                #pragma unroll
                for (int nt = 0; nt < 4; nt++)
                    mma_tf32(acc[mt][nt], af[mt], bf[nt]);
        }
        if (ch < 3) {
            const int nb = buf ^ 1;
            #pragma unroll
            for (int i = 0; i < 4; i++) {
                int r = lr + i * 32;
                *(float4*)&As_(sm, nb, r, lc) = pa[i];
                *(float4*)&Bs_(sm, nb, r, lc) = pb[i];
            }
            __syncthreads();
            buf = nb;
        }
    }

    // epilogue -> g_O (tf32-rounded)
    #pragma unroll
    for (int mt = 0; mt < 4; mt++) {
        const int row0 = p0 + wm + mt * 16 + (lane >> 2);
        #pragma unroll
        for (int nt = 0; nt < 4; nt++) {
            const int col = q0 + wn + nt * 8 + (lane & 3) * 2;
            float2 v0, v1;
            v0.x = __uint_as_float(rna_tf32(acc[mt][nt][0]));
            v0.y = __uint_as_float(rna_tf32(acc[mt][nt][1]));
            v1.x = __uint_as_float(rna_tf32(acc[mt][nt][2]));
            v1.y = __uint_as_float(rna_tf32(acc[mt][nt][3]));
            *(float2*)&g_O[(size_t)row0 * P_DIM + col]       = v0;
            *(float2*)&g_O[(size_t)(row0 + 8) * P_DIM + col] = v1;
        }
    }
}

// ============================================================================
// GEMM2: out[65536,128] = O'[65536,1024] @ woT^T  (+bo, /norm)
// A chunk (fixed i, c) = contiguous 16KB strip of g_O. 32 chunks, dbl-buffered.
// ============================================================================
__global__ void __launch_bounds__(256) gemm2_mma(const float* __restrict__ bo,
                                                 float* __restrict__ out) {
    extern __shared__ __align__(16) float sm[];
    const int tid = threadIdx.x;
    const int wid = tid >> 5, lane = tid & 31;
    const int wm = (wid & 1) * 64, wn = (wid >> 1) * 32;
    const int m0 = blockIdx.x * 128;
    const int i_idx = m0 >> 8, j0 = m0 & 255;
    const int lr = tid >> 3;
    const int lc = (tid & 7) * 4;

    float acc[4][4][4];
    #pragma unroll
    for (int a = 0; a < 4; a++)
        #pragma unroll
        for (int b = 0; b < 4; b++)
            #pragma unroll
            for (int e = 0; e < 4; e++) acc[a][b][e] = 0.f;

    float4 pa[4], pb[4];
    {
        const float* gA = &g_O[((size_t)(i_idx * 32 + 0)) * P_DIM + (size_t)j0 * 32];
        #pragma unroll
        for (int i = 0; i < 4; i++) {
            int r = lr + i * 32;
            pa[i] = *(const float4*)&gA[r * 32 + lc];
            pb[i] = *(const float4*)&g_woT[(size_t)r * 1024 + 0 * 32 + lc];
        }
        #pragma unroll
        for (int i = 0; i < 4; i++) {
            int r = lr + i * 32;
            *(float4*)&As_(sm, 0, r, lc) = pa[i];
            *(float4*)&Bs_(sm, 0, r, lc) = pb[i];
        }
    }
    __syncthreads();

    int buf = 0;
    for (int ch = 0; ch < 32; ch++) {
        if (ch < 31) {
            const int c = ch + 1;
            const float* gA = &g_O[((size_t)(i_idx * 32 + c)) * P_DIM + (size_t)j0 * 32];
            #pragma unroll
            for (int i = 0; i < 4; i++) {
                int r = lr + i * 32;
                pa[i] = *(const float4*)&gA[r * 32 + lc];
                pb[i] = *(const float4*)&g_woT[(size_t)r * 1024 + c * 32 + lc];
            }
        }
        #pragma unroll
        for (int kk = 0; kk < 4; kk++) {
            const int acol = kk * 8 + (lane & 3);
            const int arow = wm + (lane >> 2);
            uint32_t af[4][4], bf[4][2];
            #pragma unroll
            for (int mt = 0; mt < 4; mt++) {
                af[mt][0] = __float_as_uint(As_(sm, buf, arow + mt * 16,     acol));
                af[mt][1] = __float_as_uint(As_(sm, buf, arow + mt * 16 + 8, acol));
                af[mt][2] = __float_as_uint(As_(sm, buf, arow + mt * 16,     acol + 4));
                af[mt][3] = __float_as_uint(As_(sm, buf, arow + mt * 16 + 8, acol + 4));
            }
            const int brow = wn + (lane >> 2);
            #pragma unroll
            for (int nt = 0; nt < 4; nt++) {
                bf[nt][0] = __float_as_uint(Bs_(sm, buf, brow + nt * 8, acol));
                bf[nt][1] = __float_as_uint(Bs_(sm, buf, brow + nt * 8, acol + 4));
            }
            #pragma unroll
            for (int mt = 0; mt < 4; mt++)
                #pragma unroll
                for (int nt = 0; nt < 4; nt++)
                    mma_tf32(acc[mt][nt], af[mt], bf[nt]);
        }
        if (ch < 31) {
            const int nb = buf ^ 1;
            #pragma unroll
            for (int i = 0; i < 4; i++) {
                int r = lr + i * 32;
                *(float4*)&As_(sm, nb, r, lc) = pa[i];
                *(float4*)&Bs_(sm, nb, r, lc) = pb[i];
            }
            __syncthreads();
            buf = nb;
        }
    }

    // epilogue: +bo, /norm
    #pragma unroll
    for (int mt = 0; mt < 4; mt++) {
        const int row0 = m0 + wm + mt * 16 + (lane >> 2);
        const float inv0 = 1.0f / g_norm[row0];
        const float inv1 = 1.0f / g_norm[row0 + 8];
        #pragma unroll
        for (int nt = 0; nt < 4; nt++) {
            const int col = wn + nt * 8 + (lane & 3) * 2;
            const float b0v = bo[col], b1v = bo[col + 1];
            float2 v0, v1;
            v0.x = (acc[mt][nt][0] + b0v) * inv0;
            v0.y = (acc[mt][nt][1] + b1v) * inv0;
            v1.x = (acc[mt][nt][2] + b0v) * inv1;
            v1.y = (acc[mt][nt][3] + b1v) * inv1;
            *(float2*)&out[(size_t)row0 * CZ + col]       = v0;
            *(float2*)&out[(size_t)(row0 + 8) * CZ + col] = v1;
        }
    }
}

// ============================================================================
extern "C" void kernel_launch(void* const* d_in, const int* in_sizes, int n_in,
                              void* d_out, int out_size) {
    const float* m    = (const float*)d_in[0];
    const float* mask = (const float*)d_in[1];
    const float* ln_w = (const float*)d_in[2];
    const float* ln_b = (const float*)d_in[3];
    const float* w1   = (const float*)d_in[4];
    const float* b1   = (const float*)d_in[5];
    const float* w2   = (const float*)d_in[6];
    const float* b2   = (const float*)d_in[7];
    const float* wo   = (const float*)d_in[8];
    const float* bo   = (const float*)d_in[9];
    float* out = (float*)d_out;

    cudaFuncSetAttribute(ln_proj_kernel, cudaFuncAttributeMaxDynamicSharedMemorySize, 67584);
    cudaFuncSetAttribute(gemm1_mma, cudaFuncAttributeMaxDynamicSharedMemorySize, 73728);
    cudaFuncSetAttribute(gemm2_mma, cudaFuncAttributeMaxDynamicSharedMemorySize, 73728);

    ln_proj_kernel<<<2048, 256, 67584>>>(m, mask, ln_w, ln_b, w1, b1, w2, b2);
    norm_kernel<<<N_DIM, 256>>>(mask);
    woT_kernel<<<512, 256>>>(wo);

    dim3 g1(64, 64);
    gemm1_mma<<<g1, 256, 73728>>>();
    gemm2_mma<<<512, 256, 73728>>>(bo, out);
}

// round 5
// speedup vs baseline: 1.9622x; 1.1023x over previous
#include <cuda_runtime.h>
#include <cstdint>

#define S_DIM 128
#define N_DIM 256
#define CM 256
#define CH 32
#define CZ 128
#define P_DIM 8192
#define LN_EPS 1e-5f
#define OPM_EPS 1e-3f

__device__ __align__(16) float g_a[P_DIM * S_DIM];          // [p=(n,h)][s] tf32-rounded
__device__ __align__(16) float g_b[P_DIM * S_DIM];          // [q=(n,h)][s] tf32-rounded
__device__ __align__(16) float g_O[(size_t)P_DIM * P_DIM];  // [(i,c)][(j,d)] tf32-rounded
__device__ __align__(16) float g_woT[CZ * CH * CH];         // [z][k=(c,d)] tf32-rounded
__device__ float g_norm[N_DIM * N_DIM];

__device__ __forceinline__ uint32_t rna_tf32(float x) {
    uint32_t r;
    asm("cvt.rna.tf32.f32 %0, %1;" : "=r"(r) : "f"(x));
    return r;
}
__device__ __forceinline__ uint32_t smem_u32(const void* p) {
    uint32_t a;
    asm("{ .reg .u64 t; cvta.to.shared.u64 t, %1; cvt.u32.u64 %0, t; }" : "=r"(a) : "l"(p));
    return a;
}

// D += A(16x8, tf32 row) * B(8x8, tf32 col)
__device__ __forceinline__ void mma_tf32(float* c, const uint32_t* a, const uint32_t* b) {
    asm volatile(
        "mma.sync.aligned.m16n8k8.row.col.f32.tf32.tf32.f32 "
        "{%0,%1,%2,%3}, {%4,%5,%6,%7}, {%8,%9}, {%0,%1,%2,%3};\n"
        : "+f"(c[0]), "+f"(c[1]), "+f"(c[2]), "+f"(c[3])
        : "r"(a[0]), "r"(a[1]), "r"(a[2]), "r"(a[3]), "r"(b[0]), "r"(b[1]));
}

// ldmatrix x4 on fp32 data reinterpreted as b16 pairs: one instr = full tf32 fragment
__device__ __forceinline__ void ldsm_x4(uint32_t* r, uint32_t addr) {
    asm volatile("ldmatrix.sync.aligned.m8n8.x4.shared.b16 {%0,%1,%2,%3}, [%4];"
        : "=r"(r[0]), "=r"(r[1]), "=r"(r[2]), "=r"(r[3]) : "r"(addr));
}

// smem tiles: A[2][128][36], B[2][128][36] floats (73728 B total)
__device__ __forceinline__ float& As_(float* s, int buf, int m, int k) {
    return s[buf * 4608 + m * 36 + k];
}
__device__ __forceinline__ float& Bs_(float* s, int buf, int n, int k) {
    return s[9216 + buf * 4608 + n * 36 + k];
}
#define ABUF_STRIDE 18432u   // bytes between A buffers (4608 floats)
#define B_BASE_OFF  36864u   // bytes to B region (9216 floats)
#define ROW_BYTES   144u     // 36 floats

// ============================================================================
// Kernel 1: LayerNorm + dual 256->32 projection (weights cached in smem).
// ============================================================================
__global__ void __launch_bounds__(256) ln_proj_kernel(
        const float* __restrict__ m, const float* __restrict__ mask,
        const float* __restrict__ ln_w, const float* __restrict__ ln_b,
        const float* __restrict__ w1, const float* __restrict__ b1,
        const float* __restrict__ w2, const float* __restrict__ b2) {
    extern __shared__ __align__(16) float dsm[];
    float* sw1 = dsm;              // [256][32]
    float* sw2 = dsm + 8192;       // [256][32]
    float* sh_ln = dsm + 16384;    // [256]
    float* part = dsm + 16640;     // [4][64]
    __shared__ float wsum[8], wsum2[8], s_stats[2];

    const int s = blockIdx.x >> 4;
    const int grp = blockIdx.x & 15;
    const int tid = threadIdx.x;

    #pragma unroll
    for (int i = 0; i < 8; i++) {
        int f = tid + i * 256;
        *(float4*)&sw1[f * 4] = *(const float4*)&w1[f * 4];
        *(float4*)&sw2[f * 4] = *(const float4*)&w2[f * 4];
    }
    __syncthreads();

    const int g = tid >> 6, o = tid & 63, h = o & 31;
    const float* wsm = (o < 32) ? sw1 : sw2;
    const int k0 = g * 64;

    for (int r = 0; r < 16; r++) {
        const int n = grp * 16 + r;
        const int row = s * N_DIM + n;
        float x = m[(size_t)row * CM + tid];
        float v = x, v2 = x * x;
        #pragma unroll
        for (int off = 16; off > 0; off >>= 1) {
            v  += __shfl_xor_sync(0xffffffff, v,  off);
            v2 += __shfl_xor_sync(0xffffffff, v2, off);
        }
        if ((tid & 31) == 0) { wsum[tid >> 5] = v; wsum2[tid >> 5] = v2; }
        __syncthreads();
        if (tid == 0) {
            float t = 0.f, t2 = 0.f;
            #pragma unroll
            for (int i = 0; i < 8; i++) { t += wsum[i]; t2 += wsum2[i]; }
            float mu = t * (1.f / CM);
            float var = t2 * (1.f / CM) - mu * mu;
            s_stats[0] = mu; s_stats[1] = rsqrtf(var + LN_EPS);
        }
        __syncthreads();
        sh_ln[tid] = (x - s_stats[0]) * s_stats[1] * ln_w[tid] + ln_b[tid];
        __syncthreads();

        float acc = 0.f;
        #pragma unroll 16
        for (int k = k0; k < k0 + 64; k++)
            acc += sh_ln[k] * wsm[k * CH + h];
        part[g * 64 + o] = acc;
        __syncthreads();

        if (tid < 64) {
            float mk = mask[row];
            float sum = part[tid] + part[64 + tid] + part[128 + tid] + part[192 + tid];
            if (tid < 32)
                g_a[(size_t)(n * CH + tid) * S_DIM + s] =
                    __uint_as_float(rna_tf32((sum + b1[tid]) * mk));
            else
                g_b[(size_t)(n * CH + h) * S_DIM + s] =
                    __uint_as_float(rna_tf32((sum + b2[h]) * mk));
        }
        __syncthreads();
    }
}

// ============================================================================
// norm + woT
// ============================================================================
__global__ void norm_kernel(const float* __restrict__ mask) {
    const int i = blockIdx.x, j = threadIdx.x;
    __shared__ float mi[S_DIM];
    if (j < S_DIM) mi[j] = mask[j * N_DIM + i];
    __syncthreads();
    float acc = 0.f;
    #pragma unroll 8
    for (int s = 0; s < S_DIM; s++) acc += mi[s] * mask[s * N_DIM + j];
    g_norm[i * N_DIM + j] = acc + OPM_EPS;
}

__global__ void woT_kernel(const float* __restrict__ wo) {
    int idx = blockIdx.x * 256 + threadIdx.x;   // 131072
    int z = idx >> 10, k = idx & 1023;
    g_woT[idx] = __uint_as_float(rna_tf32(wo[k * CZ + z]));
}

// ============================================================================
// GEMM1: O[8192,8192] = A[8192,128] * B[8192,128]^T via mma.sync tf32 + ldmatrix
// ============================================================================
__global__ void __launch_bounds__(256) gemm1_mma() {
    extern __shared__ __align__(16) float sm[];
    const int tid = threadIdx.x;
    const int wid = tid >> 5, lane = tid & 31;
    const int wm = (wid & 1) * 64, wn = (wid >> 1) * 32;
    const int p0 = blockIdx.y * 128, q0 = blockIdx.x * 128;
    const int lr = tid >> 3;            // 0..31 (+32*i)
    const int lc = (tid & 7) * 4;       // 0..28

    // ldmatrix per-lane base addresses
    const int lg = lane >> 3, lrow = lane & 7;
    const uint32_t sbase = smem_u32(sm);
    const uint32_t a_base = sbase + (uint32_t)(wm + (lg & 1) * 8 + lrow) * ROW_BYTES
                          + (uint32_t)(lg >> 1) * 16;
    const uint32_t b_base = sbase + B_BASE_OFF
                          + (uint32_t)(wn + (lg >> 1) * 8 + lrow) * ROW_BYTES
                          + (uint32_t)(lg & 1) * 16;

    float acc[4][4][4];
    #pragma unroll
    for (int a = 0; a < 4; a++)
        #pragma unroll
        for (int b = 0; b < 4; b++)
            #pragma unroll
            for (int e = 0; e < 4; e++) acc[a][b][e] = 0.f;

    float4 pa[4], pb[4];
    #pragma unroll
    for (int i = 0; i < 4; i++) {
        int r = lr + i * 32;
        pa[i] = *(const float4*)&g_a[(size_t)(p0 + r) * S_DIM + lc];
        pb[i] = *(const float4*)&g_b[(size_t)(q0 + r) * S_DIM + lc];
    }
    #pragma unroll
    for (int i = 0; i < 4; i++) {
        int r = lr + i * 32;
        *(float4*)&As_(sm, 0, r, lc) = pa[i];
        *(float4*)&Bs_(sm, 0, r, lc) = pb[i];
    }
    __syncthreads();

    int buf = 0;
    #pragma unroll
    for (int ch = 0; ch < 4; ch++) {
        if (ch < 3) {
            const int kb = (ch + 1) * 32;
            #pragma unroll
            for (int i = 0; i < 4; i++) {
                int r = lr + i * 32;
                pa[i] = *(const float4*)&g_a[(size_t)(p0 + r) * S_DIM + kb + lc];
                pb[i] = *(const float4*)&g_b[(size_t)(q0 + r) * S_DIM + kb + lc];
            }
        }
        const uint32_t boff = (uint32_t)buf * ABUF_STRIDE;
        #pragma unroll
        for (int kk = 0; kk < 4; kk++) {
            uint32_t af[4][4], bf[4][2];
            #pragma unroll
            for (int mt = 0; mt < 4; mt++)
                ldsm_x4(af[mt], a_base + boff + kk * 32 + mt * (16 * ROW_BYTES));
            #pragma unroll
            for (int pr = 0; pr < 2; pr++) {
                uint32_t t[4];
                ldsm_x4(t, b_base + boff + kk * 32 + pr * (16 * ROW_BYTES));
                bf[2 * pr][0] = t[0]; bf[2 * pr][1] = t[1];
                bf[2 * pr + 1][0] = t[2]; bf[2 * pr + 1][1] = t[3];
            }
            #pragma unroll
            for (int mt = 0; mt < 4; mt++)
                #pragma unroll
                for (int nt = 0; nt < 4; nt++)
                    mma_tf32(acc[mt][nt], af[mt], bf[nt]);
        }
        if (ch < 3) {
            const int nb = buf ^ 1;
            #pragma unroll
            for (int i = 0; i < 4; i++) {
                int r = lr + i * 32;
                *(float4*)&As_(sm, nb, r, lc) = pa[i];
                *(float4*)&Bs_(sm, nb, r, lc) = pb[i];
            }
            __syncthreads();
            buf = nb;
        }
    }

    // epilogue -> g_O (tf32-rounded)
    #pragma unroll
    for (int mt = 0; mt < 4; mt++) {
        const int row0 = p0 + wm + mt * 16 + (lane >> 2);
        #pragma unroll
        for (int nt = 0; nt < 4; nt++) {
            const int col = q0 + wn + nt * 8 + (lane & 3) * 2;
            float2 v0, v1;
            v0.x = __uint_as_float(rna_tf32(acc[mt][nt][0]));
            v0.y = __uint_as_float(rna_tf32(acc[mt][nt][1]));
            v1.x = __uint_as_float(rna_tf32(acc[mt][nt][2]));
            v1.y = __uint_as_float(rna_tf32(acc[mt][nt][3]));
            *(float2*)&g_O[(size_t)row0 * P_DIM + col]       = v0;
            *(float2*)&g_O[(size_t)(row0 + 8) * P_DIM + col] = v1;
        }
    }
}

// ============================================================================
// GEMM2: out[65536,128] = O'[65536,1024] @ woT^T  (+bo, /norm)
// ============================================================================
__global__ void __launch_bounds__(256) gemm2_mma(const float* __restrict__ bo,
                                                 float* __restrict__ out) {
    extern __shared__ __align__(16) float sm[];
    const int tid = threadIdx.x;
    const int wid = tid >> 5, lane = tid & 31;
    const int wm = (wid & 1) * 64, wn = (wid >> 1) * 32;
    const int m0 = blockIdx.x * 128;
    const int i_idx = m0 >> 8, j0 = m0 & 255;
    const int lr = tid >> 3;
    const int lc = (tid & 7) * 4;

    const int lg = lane >> 3, lrow = lane & 7;
    const uint32_t sbase = smem_u32(sm);
    const uint32_t a_base = sbase + (uint32_t)(wm + (lg & 1) * 8 + lrow) * ROW_BYTES
                          + (uint32_t)(lg >> 1) * 16;
    const uint32_t b_base = sbase + B_BASE_OFF
                          + (uint32_t)(wn + (lg >> 1) * 8 + lrow) * ROW_BYTES
                          + (uint32_t)(lg & 1) * 16;

    float acc[4][4][4];
    #pragma unroll
    for (int a = 0; a < 4; a++)
        #pragma unroll
        for (int b = 0; b < 4; b++)
            #pragma unroll
            for (int e = 0; e < 4; e++) acc[a][b][e] = 0.f;

    float4 pa[4], pb[4];
    {
        const float* gA = &g_O[((size_t)(i_idx * 32 + 0)) * P_DIM + (size_t)j0 * 32];
        #pragma unroll
        for (int i = 0; i < 4; i++) {
            int r = lr + i * 32;
            pa[i] = *(const float4*)&gA[r * 32 + lc];
            pb[i] = *(const float4*)&g_woT[(size_t)r * 1024 + 0 * 32 + lc];
        }
        #pragma unroll
        for (int i = 0; i < 4; i++) {
            int r = lr + i * 32;
            *(float4*)&As_(sm, 0, r, lc) = pa[i];
            *(float4*)&Bs_(sm, 0, r, lc) = pb[i];
        }
    }
    __syncthreads();

    int buf = 0;
    for (int ch = 0; ch < 32; ch++) {
        if (ch < 31) {
            const int c = ch + 1;
            const float* gA = &g_O[((size_t)(i_idx * 32 + c)) * P_DIM + (size_t)j0 * 32];
            #pragma unroll
            for (int i = 0; i < 4; i++) {
                int r = lr + i * 32;
                pa[i] = *(const float4*)&gA[r * 32 + lc];
                pb[i] = *(const float4*)&g_woT[(size_t)r * 1024 + c * 32 + lc];
            }
        }
        const uint32_t boff = (uint32_t)buf * ABUF_STRIDE;
        #pragma unroll
        for (int kk = 0; kk < 4; kk++) {
            uint32_t af[4][4], bf[4][2];
            #pragma unroll
            for (int mt = 0; mt < 4; mt++)
                ldsm_x4(af[mt], a_base + boff + kk * 32 + mt * (16 * ROW_BYTES));
            #pragma unroll
            for (int pr = 0; pr < 2; pr++) {
                uint32_t t[4];
                ldsm_x4(t, b_base + boff + kk * 32 + pr * (16 * ROW_BYTES));
                bf[2 * pr][0] = t[0]; bf[2 * pr][1] = t[1];
                bf[2 * pr + 1][0] = t[2]; bf[2 * pr + 1][1] = t[3];
            }
            #pragma unroll
            for (int mt = 0; mt < 4; mt++)
                #pragma unroll
                for (int nt = 0; nt < 4; nt++)
                    mma_tf32(acc[mt][nt], af[mt], bf[nt]);
        }
        if (ch < 31) {
            const int nb = buf ^ 1;
            #pragma unroll
            for (int i = 0; i < 4; i++) {
                int r = lr + i * 32;
                *(float4*)&As_(sm, nb, r, lc) = pa[i];
                *(float4*)&Bs_(sm, nb, r, lc) = pb[i];
            }
            __syncthreads();
            buf = nb;
        }
    }

    // epilogue: +bo, /norm
    #pragma unroll
    for (int mt = 0; mt < 4; mt++) {
        const int row0 = m0 + wm + mt * 16 + (lane >> 2);
        const float inv0 = 1.0f / g_norm[row0];
        const float inv1 = 1.0f / g_norm[row0 + 8];
        #pragma unroll
        for (int nt = 0; nt < 4; nt++) {
            const int col = wn + nt * 8 + (lane & 3) * 2;
            const float b0v = bo[col], b1v = bo[col + 1];
            float2 v0, v1;
            v0.x = (acc[mt][nt][0] + b0v) * inv0;
            v0.y = (acc[mt][nt][1] + b1v) * inv0;
            v1.x = (acc[mt][nt][2] + b0v) * inv1;
            v1.y = (acc[mt][nt][3] + b1v) * inv1;
            *(float2*)&out[(size_t)row0 * CZ + col]       = v0;
            *(float2*)&out[(size_t)(row0 + 8) * CZ + col] = v1;
        }
    }
}

// ============================================================================
extern "C" void kernel_launch(void* const* d_in, const int* in_sizes, int n_in,
                              void* d_out, int out_size) {
    const float* m    = (const float*)d_in[0];
    const float* mask = (const float*)d_in[1];
    const float* ln_w = (const float*)d_in[2];
    const float* ln_b = (const float*)d_in[3];
    const float* w1   = (const float*)d_in[4];
    const float* b1   = (const float*)d_in[5];
    const float* w2   = (const float*)d_in[6];
    const float* b2   = (const float*)d_in[7];
    const float* wo   = (const float*)d_in[8];
    const float* bo   = (const float*)d_in[9];
    float* out = (float*)d_out;

    cudaFuncSetAttribute(ln_proj_kernel, cudaFuncAttributeMaxDynamicSharedMemorySize, 67584);
    cudaFuncSetAttribute(gemm1_mma, cudaFuncAttributeMaxDynamicSharedMemorySize, 73728);
    cudaFuncSetAttribute(gemm2_mma, cudaFuncAttributeMaxDynamicSharedMemorySize, 73728);

    ln_proj_kernel<<<2048, 256, 67584>>>(m, mask, ln_w, ln_b, w1, b1, w2, b2);
    norm_kernel<<<N_DIM, 256>>>(mask);
    woT_kernel<<<512, 256>>>(wo);

    dim3 g1(64, 64);
    gemm1_mma<<<g1, 256, 73728>>>();
    gemm2_mma<<<512, 256, 73728>>>(bo, out);
}

// round 6
// speedup vs baseline: 2.0875x; 1.0638x over previous
#include <cuda_runtime.h>
#include <cstdint>

#define S_DIM 128
#define N_DIM 256
#define CM 256
#define CH 32
#define CZ 128
#define P_DIM 8192
#define LN_EPS 1e-5f
#define OPM_EPS 1e-3f

__device__ __align__(16) float g_a[P_DIM * S_DIM];          // [p=(n,h)][s] tf32-rounded
__device__ __align__(16) float g_b[P_DIM * S_DIM];          // [q=(n,h)][s] tf32-rounded
__device__ __align__(16) float g_O[(size_t)P_DIM * P_DIM];  // [(i,c)][(j,d)] tf32-rounded
__device__ __align__(16) float g_woT[CZ * CH * CH];         // [z][k=(c,d)] tf32-rounded
__device__ float g_norm[N_DIM * N_DIM];

__device__ __forceinline__ uint32_t rna_tf32(float x) {
    uint32_t r;
    asm("cvt.rna.tf32.f32 %0, %1;" : "=r"(r) : "f"(x));
    return r;
}
__device__ __forceinline__ uint32_t smem_u32(const void* p) {
    uint32_t a;
    asm("{ .reg .u64 t; cvta.to.shared.u64 t, %1; cvt.u32.u64 %0, t; }" : "=r"(a) : "l"(p));
    return a;
}
__device__ __forceinline__ void mma_tf32(float* c, const uint32_t* a, const uint32_t* b) {
    asm volatile(
        "mma.sync.aligned.m16n8k8.row.col.f32.tf32.tf32.f32 "
        "{%0,%1,%2,%3}, {%4,%5,%6,%7}, {%8,%9}, {%0,%1,%2,%3};\n"
        : "+f"(c[0]), "+f"(c[1]), "+f"(c[2]), "+f"(c[3])
        : "r"(a[0]), "r"(a[1]), "r"(a[2]), "r"(a[3]), "r"(b[0]), "r"(b[1]));
}
__device__ __forceinline__ void ldsm_x4(uint32_t* r, uint32_t addr) {
    asm volatile("ldmatrix.sync.aligned.m8n8.x4.shared.b16 {%0,%1,%2,%3}, [%4];"
        : "=r"(r[0]), "=r"(r[1]), "=r"(r[2]), "=r"(r[3]) : "r"(addr));
}
__device__ __forceinline__ void cp16(uint32_t d, const float* s) {
    asm volatile("cp.async.cg.shared.global [%0], [%1], 16;" :: "r"(d), "l"(s));
}
#define CP_COMMIT() asm volatile("cp.async.commit_group;" ::: "memory")
#define CP_WAIT1()  asm volatile("cp.async.wait_group 1;" ::: "memory")

// Stage layout (floats): [A 128x36 | B 128x36] per stage, 3 stages.
#define ROW_BYTES   144u
#define STAGE_BYTES 36864u
#define B_OFF       18432u
#define SMEM_BYTES  (3 * 36864)

// one 32-K chunk of 128x128x32 with 64x64 warp tiles (4 warps)
__device__ __forceinline__ void mma_chunk(uint32_t a_base, uint32_t b_base,
                                          float acc[4][8][4]) {
    #pragma unroll
    for (int kk = 0; kk < 4; kk++) {
        uint32_t af[4][4], bf[8][2];
        #pragma unroll
        for (int mt = 0; mt < 4; mt++)
            ldsm_x4(af[mt], a_base + kk * 32 + mt * (16 * ROW_BYTES));
        #pragma unroll
        for (int pr = 0; pr < 4; pr++) {
            uint32_t t[4];
            ldsm_x4(t, b_base + kk * 32 + pr * (16 * ROW_BYTES));
            bf[2 * pr][0] = t[0]; bf[2 * pr][1] = t[1];
            bf[2 * pr + 1][0] = t[2]; bf[2 * pr + 1][1] = t[3];
        }
        #pragma unroll
        for (int mt = 0; mt < 4; mt++)
            #pragma unroll
            for (int nt = 0; nt < 8; nt++)
                mma_tf32(acc[mt][nt], af[mt], bf[nt]);
    }
}

// ============================================================================
// Kernel 1: LayerNorm + dual 256->32 projection (weights cached in smem).
// ============================================================================
__global__ void __launch_bounds__(256) ln_proj_kernel(
        const float* __restrict__ m, const float* __restrict__ mask,
        const float* __restrict__ ln_w, const float* __restrict__ ln_b,
        const float* __restrict__ w1, const float* __restrict__ b1,
        const float* __restrict__ w2, const float* __restrict__ b2) {
    extern __shared__ __align__(16) float dsm[];
    float* sw1 = dsm;              // [256][32]
    float* sw2 = dsm + 8192;       // [256][32]
    float* sh_ln = dsm + 16384;    // [256]
    float* part = dsm + 16640;     // [4][64]
    __shared__ float wsum[8], wsum2[8], s_stats[2];

    const int s = blockIdx.x >> 4;
    const int grp = blockIdx.x & 15;
    const int tid = threadIdx.x;

    #pragma unroll
    for (int i = 0; i < 8; i++) {
        int f = tid + i * 256;
        *(float4*)&sw1[f * 4] = *(const float4*)&w1[f * 4];
        *(float4*)&sw2[f * 4] = *(const float4*)&w2[f * 4];
    }
    __syncthreads();

    const int g = tid >> 6, o = tid & 63, h = o & 31;
    const float* wsm = (o < 32) ? sw1 : sw2;
    const int k0 = g * 64;

    for (int r = 0; r < 16; r++) {
        const int n = grp * 16 + r;
        const int row = s * N_DIM + n;
        float x = m[(size_t)row * CM + tid];
        float v = x, v2 = x * x;
        #pragma unroll
        for (int off = 16; off > 0; off >>= 1) {
            v  += __shfl_xor_sync(0xffffffff, v,  off);
            v2 += __shfl_xor_sync(0xffffffff, v2, off);
        }
        if ((tid & 31) == 0) { wsum[tid >> 5] = v; wsum2[tid >> 5] = v2; }
        __syncthreads();
        if (tid == 0) {
            float t = 0.f, t2 = 0.f;
            #pragma unroll
            for (int i = 0; i < 8; i++) { t += wsum[i]; t2 += wsum2[i]; }
            float mu = t * (1.f / CM);
            float var = t2 * (1.f / CM) - mu * mu;
            s_stats[0] = mu; s_stats[1] = rsqrtf(var + LN_EPS);
        }
        __syncthreads();
        sh_ln[tid] = (x - s_stats[0]) * s_stats[1] * ln_w[tid] + ln_b[tid];
        __syncthreads();

        float acc = 0.f;
        #pragma unroll 16
        for (int k = k0; k < k0 + 64; k++)
            acc += sh_ln[k] * wsm[k * CH + h];
        part[g * 64 + o] = acc;
        __syncthreads();

        if (tid < 64) {
            float mk = mask[row];
            float sum = part[tid] + part[64 + tid] + part[128 + tid] + part[192 + tid];
            if (tid < 32)
                g_a[(size_t)(n * CH + tid) * S_DIM + s] =
                    __uint_as_float(rna_tf32((sum + b1[tid]) * mk));
            else
                g_b[(size_t)(n * CH + h) * S_DIM + s] =
                    __uint_as_float(rna_tf32((sum + b2[h]) * mk));
        }
        __syncthreads();
    }
}

// ============================================================================
// norm + woT
// ============================================================================
__global__ void norm_kernel(const float* __restrict__ mask) {
    const int i = blockIdx.x, j = threadIdx.x;
    __shared__ float mi[S_DIM];
    if (j < S_DIM) mi[j] = mask[j * N_DIM + i];
    __syncthreads();
    float acc = 0.f;
    #pragma unroll 8
    for (int s = 0; s < S_DIM; s++) acc += mi[s] * mask[s * N_DIM + j];
    g_norm[i * N_DIM + j] = acc + OPM_EPS;
}

__global__ void woT_kernel(const float* __restrict__ wo) {
    int idx = blockIdx.x * 256 + threadIdx.x;   // 131072
    int z = idx >> 10, k = idx & 1023;
    g_woT[idx] = __uint_as_float(rna_tf32(wo[k * CZ + z]));
}

// ============================================================================
// GEMM1: O[8192,8192] = A[8192,128]*B[8192,128]^T.  128x128 CTA, 4 warps,
// 64x64 warp tiles, cp.async 3-stage pipeline, NC=4 chunks.
// ============================================================================
__global__ void __launch_bounds__(128) gemm1_mma() {
    extern __shared__ __align__(16) float sm[];
    const uint32_t sbase = smem_u32(sm);
    const int tid = threadIdx.x, wid = tid >> 5, lane = tid & 31;
    const int wm = (wid & 1) * 64, wn = (wid >> 1) * 64;
    const int p0 = blockIdx.y * 128, q0 = blockIdx.x * 128;
    const int lg = lane >> 3, lrow = lane & 7;
    const uint32_t a_lo = (uint32_t)(wm + (lg & 1) * 8 + lrow) * ROW_BYTES
                        + (uint32_t)(lg >> 1) * 16;
    const uint32_t b_lo = B_OFF + (uint32_t)(wn + (lg >> 1) * 8 + lrow) * ROW_BYTES
                        + (uint32_t)(lg & 1) * 16;

    float acc[4][8][4];
    #pragma unroll
    for (int a = 0; a < 4; a++)
        #pragma unroll
        for (int b = 0; b < 8; b++)
            #pragma unroll
            for (int e = 0; e < 4; e++) acc[a][b][e] = 0.f;

    auto copy1 = [&](int ch, int st) {
        const int kb = ch * 32;
        const uint32_t dA = sbase + st * STAGE_BYTES;
        const uint32_t dB = dA + B_OFF;
        #pragma unroll
        for (int i = 0; i < 8; i++) {
            int f = tid + i * 128, rr = f >> 3, cc = f & 7;
            cp16(dA + rr * ROW_BYTES + cc * 16,
                 &g_a[(size_t)(p0 + rr) * S_DIM + kb + cc * 4]);
            cp16(dB + rr * ROW_BYTES + cc * 16,
                 &g_b[(size_t)(q0 + rr) * S_DIM + kb + cc * 4]);
        }
    };

    copy1(0, 0); CP_COMMIT();
    copy1(1, 1); CP_COMMIT();

    #pragma unroll
    for (int ch = 0; ch < 4; ch++) {
        CP_WAIT1();
        __syncthreads();
        const uint32_t so = sbase + (uint32_t)(ch % 3) * STAGE_BYTES;
        mma_chunk(so + a_lo, so + b_lo, acc);
        if (ch + 2 < 4) copy1(ch + 2, (ch + 2) % 3);
        CP_COMMIT();
    }

    // epilogue -> g_O (tf32-rounded)
    #pragma unroll
    for (int mt = 0; mt < 4; mt++) {
        const int row0 = p0 + wm + mt * 16 + (lane >> 2);
        #pragma unroll
        for (int nt = 0; nt < 8; nt++) {
            const int col = q0 + wn + nt * 8 + (lane & 3) * 2;
            float2 v0, v1;
            v0.x = __uint_as_float(rna_tf32(acc[mt][nt][0]));
            v0.y = __uint_as_float(rna_tf32(acc[mt][nt][1]));
            v1.x = __uint_as_float(rna_tf32(acc[mt][nt][2]));
            v1.y = __uint_as_float(rna_tf32(acc[mt][nt][3]));
            *(float2*)&g_O[(size_t)row0 * P_DIM + col]       = v0;
            *(float2*)&g_O[(size_t)(row0 + 8) * P_DIM + col] = v1;
        }
    }
}

// ============================================================================
// GEMM2: out[65536,128] = O'[65536,1024] @ woT^T (+bo, /norm).
// 128x128 CTA, 4 warps, 64x64 warp tiles, cp.async 3-stage, NC=32 chunks.
// ============================================================================
__global__ void __launch_bounds__(128) gemm2_mma(const float* __restrict__ bo,
                                                 float* __restrict__ out) {
    extern __shared__ __align__(16) float sm[];
    const uint32_t sbase = smem_u32(sm);
    const int tid = threadIdx.x, wid = tid >> 5, lane = tid & 31;
    const int wm = (wid & 1) * 64, wn = (wid >> 1) * 64;
    const int m0 = blockIdx.x * 128;
    const int i_idx = m0 >> 8, j0 = m0 & 255;
    const int lg = lane >> 3, lrow = lane & 7;
    const uint32_t a_lo = (uint32_t)(wm + (lg & 1) * 8 + lrow) * ROW_BYTES
                        + (uint32_t)(lg >> 1) * 16;
    const uint32_t b_lo = B_OFF + (uint32_t)(wn + (lg >> 1) * 8 + lrow) * ROW_BYTES
                        + (uint32_t)(lg & 1) * 16;

    float acc[4][8][4];
    #pragma unroll
    for (int a = 0; a < 4; a++)
        #pragma unroll
        for (int b = 0; b < 8; b++)
            #pragma unroll
            for (int e = 0; e < 4; e++) acc[a][b][e] = 0.f;

    auto copy1 = [&](int ch, int st) {
        const float* gA = &g_O[((size_t)(i_idx * 32 + ch)) * P_DIM + (size_t)j0 * 32];
        const uint32_t dA = sbase + st * STAGE_BYTES;
        const uint32_t dB = dA + B_OFF;
        #pragma unroll
        for (int i = 0; i < 8; i++) {
            int f = tid + i * 128, rr = f >> 3, cc = f & 7;
            cp16(dA + rr * ROW_BYTES + cc * 16, &gA[f * 4]);
            cp16(dB + rr * ROW_BYTES + cc * 16,
                 &g_woT[(size_t)rr * 1024 + ch * 32 + cc * 4]);
        }
    };

    copy1(0, 0); CP_COMMIT();
    copy1(1, 1); CP_COMMIT();

    int st = 0;
    for (int ch = 0; ch < 32; ch++) {
        CP_WAIT1();
        __syncthreads();
        const uint32_t so = sbase + (uint32_t)st * STAGE_BYTES;
        mma_chunk(so + a_lo, so + b_lo, acc);
        if (ch + 2 < 32) {
            int ns = st + 2; if (ns >= 3) ns -= 3;
            copy1(ch + 2, ns);
        }
        CP_COMMIT();
        if (++st == 3) st = 0;
    }

    // epilogue: +bo, /norm
    #pragma unroll
    for (int mt = 0; mt < 4; mt++) {
        const int row0 = m0 + wm + mt * 16 + (lane >> 2);
        const float inv0 = 1.0f / g_norm[row0];
        const float inv1 = 1.0f / g_norm[row0 + 8];
        #pragma unroll
        for (int nt = 0; nt < 8; nt++) {
            const int col = wn + nt * 8 + (lane & 3) * 2;
            const float b0v = bo[col], b1v = bo[col + 1];
            float2 v0, v1;
            v0.x = (acc[mt][nt][0] + b0v) * inv0;
            v0.y = (acc[mt][nt][1] + b1v) * inv0;
            v1.x = (acc[mt][nt][2] + b0v) * inv1;
            v1.y = (acc[mt][nt][3] + b1v) * inv1;
            *(float2*)&out[(size_t)row0 * CZ + col]       = v0;
            *(float2*)&out[(size_t)(row0 + 8) * CZ + col] = v1;
        }
    }
}

// ============================================================================
extern "C" void kernel_launch(void* const* d_in, const int* in_sizes, int n_in,
                              void* d_out, int out_size) {
    const float* m    = (const float*)d_in[0];
    const float* mask = (const float*)d_in[1];
    const float* ln_w = (const float*)d_in[2];
    const float* ln_b = (const float*)d_in[3];
    const float* w1   = (const float*)d_in[4];
    const float* b1   = (const float*)d_in[5];
    const float* w2   = (const float*)d_in[6];
    const float* b2   = (const float*)d_in[7];
    const float* wo   = (const float*)d_in[8];
    const float* bo   = (const float*)d_in[9];
    float* out = (float*)d_out;

    cudaFuncSetAttribute(ln_proj_kernel, cudaFuncAttributeMaxDynamicSharedMemorySize, 67584);
    cudaFuncSetAttribute(gemm1_mma, cudaFuncAttributeMaxDynamicSharedMemorySize, SMEM_BYTES);
    cudaFuncSetAttribute(gemm2_mma, cudaFuncAttributeMaxDynamicSharedMemorySize, SMEM_BYTES);

    ln_proj_kernel<<<2048, 256, 67584>>>(m, mask, ln_w, ln_b, w1, b1, w2, b2);
    norm_kernel<<<N_DIM, 256>>>(mask);
    woT_kernel<<<512, 256>>>(wo);

    dim3 g1(64, 64);
    gemm1_mma<<<g1, 128, SMEM_BYTES>>>();
    gemm2_mma<<<512, 128, SMEM_BYTES>>>(bo, out);
}